// round 1
// baseline (speedup 1.0000x reference)
#include <cuda_runtime.h>
#include <math.h>

#define D_MODEL 1024
#define SEQ     2048
#define BATCH   2
#define NHEAD   16
#define HD      64
#define MTOT    (BATCH * SEQ)   // 4096
#define BH      (BATCH * NHEAD) // 32

// Scratch (allocation-free rule: __device__ globals)
__device__ float g_Q[(size_t)BH * SEQ * HD];   // [bh, t, hd]
__device__ float g_K[(size_t)BH * SEQ * HD];
__device__ float g_V[(size_t)BH * SEQ * HD];
__device__ float g_A[(size_t)MTOT * D_MODEL];  // attention out, [4096, 1024]

// ---------------------------------------------------------------------------
// GEMM: out = X[M,K] * W[K,N] + bias[N]
// MODE 0: out row-major [M,N]
// MODE 1: scatter to [bh, t, hd] layout:
//   m -> (bb = m/SEQ, t = m%SEQ); n -> (h = n/HD, hd = n%HD)
//   out[((bb*NHEAD + h)*SEQ + t)*HD + hd]
// Tiling: 64x64 block, BK=16, 256 threads, 4x4 per thread.
// ---------------------------------------------------------------------------
template <int MODE>
__global__ void __launch_bounds__(256) gemm_bias_kernel(
    const float* __restrict__ X, const float* __restrict__ W,
    const float* __restrict__ bias, float* __restrict__ out)
{
    const int M = MTOT, N = D_MODEL, K = D_MODEL;
    (void)M;
    __shared__ float Ast[16][64];   // transposed A tile [k][m]
    __shared__ float Bs[16][64];    // B tile [k][n]

    const int tid = threadIdx.x;
    const int tx = tid & 15, ty = tid >> 4;
    const int m0 = blockIdx.y * 64, n0 = blockIdx.x * 64;

    const float* Xp = X + (size_t)m0 * K;
    const float* Wp = W + n0;

    const int la = tid * 4;
    const int ar = la >> 4, ac = la & 15;   // A tile: row 0..63, col {0,4,8,12}
    const int br = la >> 6, bc = la & 63;   // B tile: row 0..15, col mult of 4

    float acc[4][4] = {};

    for (int k0 = 0; k0 < K; k0 += 16) {
        float4 av = *(const float4*)&Xp[(size_t)ar * K + k0 + ac];
        Ast[ac + 0][ar] = av.x;
        Ast[ac + 1][ar] = av.y;
        Ast[ac + 2][ar] = av.z;
        Ast[ac + 3][ar] = av.w;
        *(float4*)&Bs[br][bc] = *(const float4*)&Wp[(size_t)(k0 + br) * N + bc];
        __syncthreads();

#pragma unroll
        for (int kk = 0; kk < 16; kk++) {
            float4 a4 = *(const float4*)&Ast[kk][ty * 4];
            float4 b4 = *(const float4*)&Bs[kk][tx * 4];
            float a[4] = {a4.x, a4.y, a4.z, a4.w};
            float b[4] = {b4.x, b4.y, b4.z, b4.w};
#pragma unroll
            for (int i = 0; i < 4; i++)
#pragma unroll
                for (int j = 0; j < 4; j++)
                    acc[i][j] = fmaf(a[i], b[j], acc[i][j]);
        }
        __syncthreads();
    }

#pragma unroll
    for (int i = 0; i < 4; i++) {
        const int m = m0 + ty * 4 + i;
#pragma unroll
        for (int j = 0; j < 4; j++) {
            const int n = n0 + tx * 4 + j;
            const float v = acc[i][j] + bias[n];
            if (MODE == 0) {
                out[(size_t)m * N + n] = v;
            } else {
                const int bb = m >> 11;        // m / SEQ
                const int t  = m & (SEQ - 1);
                const int h  = n >> 6;         // n / HD
                const int hd = n & (HD - 1);
                out[(((size_t)(bb * NHEAD + h)) * SEQ + t) * HD + hd] = v;
            }
        }
    }
}

// ---------------------------------------------------------------------------
// Flash-style attention. Q/K/V: [bh, SEQ, HD] fp32.
// Block: 64 q-rows x full head, 256 threads (16x16, 4x4 per thread).
// Online softmax over 32 k-tiles of 64.
// Output scattered to g_A [4096, 1024] row-major (bb*SEQ+t, h*HD+hd).
// Dynamic smem: Qs[64][64] | union(Ks[64][65], Ps[64][64]) | Vs[64][64]
// ---------------------------------------------------------------------------
#define ATTN_SMEM_FLOATS (64 * 64 + 64 * 65 + 64 * 64)  // 12352
#define ATTN_SMEM_BYTES  (ATTN_SMEM_FLOATS * 4)         // 49408

__global__ void __launch_bounds__(256) attn_kernel(
    const float* __restrict__ Q, const float* __restrict__ K,
    const float* __restrict__ V, float* __restrict__ out)
{
    extern __shared__ float sm[];
    float* Qs = sm;                  // [64][64]
    float* Ks = sm + 64 * 64;        // [64][65]  (padded rows)
    float* Ps = Ks;                  // [64][64]  (union with Ks; phase-separated)
    float* Vs = Ks + 64 * 65;        // [64][64]

    const int tid = threadIdx.x;
    const int tx = tid & 15, ty = tid >> 4;
    const int bh = blockIdx.y;
    const int q0 = blockIdx.x * 64;

    const float* Qp = Q + ((size_t)bh * SEQ + q0) * HD;
    const float* Kp = K + (size_t)bh * SEQ * HD;
    const float* Vp = V + (size_t)bh * SEQ * HD;

    // Load Q tile, folding in softmax scale 1/sqrt(64) = 0.125
    for (int i = tid * 4; i < 64 * HD; i += 256 * 4) {
        const int r = i >> 6, c = i & 63;
        float4 v4 = *(const float4*)&Qp[(size_t)r * HD + c];
        v4.x *= 0.125f; v4.y *= 0.125f; v4.z *= 0.125f; v4.w *= 0.125f;
        *(float4*)&Qs[r * 64 + c] = v4;
    }

    float m_[4], l_[4], o_[4][4];
#pragma unroll
    for (int i = 0; i < 4; i++) {
        m_[i] = -1e30f;
        l_[i] = 0.0f;
#pragma unroll
        for (int j = 0; j < 4; j++) o_[i][j] = 0.0f;
    }
    __syncthreads();

    for (int kt = 0; kt < SEQ; kt += 64) {
        // Load K (padded, scalar stores) and V (vector stores) tiles
        for (int i = tid * 4; i < 64 * HD; i += 256 * 4) {
            const int r = i >> 6, c = i & 63;
            float4 kv = *(const float4*)&Kp[(size_t)(kt + r) * HD + c];
            Ks[r * 65 + c + 0] = kv.x;
            Ks[r * 65 + c + 1] = kv.y;
            Ks[r * 65 + c + 2] = kv.z;
            Ks[r * 65 + c + 3] = kv.w;
            *(float4*)&Vs[r * 64 + c] = *(const float4*)&Vp[(size_t)(kt + r) * HD + c];
        }
        __syncthreads();

        // S = Q * K^T (scaled)
        float s[4][4] = {};
#pragma unroll 8
        for (int d = 0; d < 64; d++) {
            float a[4], b[4];
#pragma unroll
            for (int i = 0; i < 4; i++) a[i] = Qs[(ty * 4 + i) * 64 + d];
#pragma unroll
            for (int j = 0; j < 4; j++) b[j] = Ks[(tx * 4 + j) * 65 + d];
#pragma unroll
            for (int i = 0; i < 4; i++)
#pragma unroll
                for (int j = 0; j < 4; j++)
                    s[i][j] = fmaf(a[i], b[j], s[i][j]);
        }
        __syncthreads();   // all Ks reads done before Ps (same memory) is written

        // Online softmax update + write P tile
#pragma unroll
        for (int i = 0; i < 4; i++) {
            float mx = fmaxf(fmaxf(s[i][0], s[i][1]), fmaxf(s[i][2], s[i][3]));
#pragma unroll
            for (int o = 1; o < 16; o <<= 1)
                mx = fmaxf(mx, __shfl_xor_sync(0xffffffffu, mx, o));
            const float mnew = fmaxf(m_[i], mx);
            const float alpha = __expf(m_[i] - mnew);
            float p[4];
            float rs = 0.0f;
#pragma unroll
            for (int j = 0; j < 4; j++) {
                p[j] = __expf(s[i][j] - mnew);
                rs += p[j];
            }
#pragma unroll
            for (int o = 1; o < 16; o <<= 1)
                rs += __shfl_xor_sync(0xffffffffu, rs, o);
            l_[i] = l_[i] * alpha + rs;
            m_[i] = mnew;
#pragma unroll
            for (int j = 0; j < 4; j++) {
                o_[i][j] *= alpha;
                Ps[(ty * 4 + i) * 64 + tx * 4 + j] = p[j];
            }
        }
        __syncthreads();

        // O += P * V
#pragma unroll 8
        for (int k = 0; k < 64; k++) {
            float a[4];
#pragma unroll
            for (int i = 0; i < 4; i++) a[i] = Ps[(ty * 4 + i) * 64 + k];
            const float4 b4 = *(const float4*)&Vs[k * 64 + tx * 4];
            const float b[4] = {b4.x, b4.y, b4.z, b4.w};
#pragma unroll
            for (int i = 0; i < 4; i++)
#pragma unroll
                for (int j = 0; j < 4; j++)
                    o_[i][j] = fmaf(a[i], b[j], o_[i][j]);
        }
        __syncthreads();
    }

    // Normalize and scatter to [4096, 1024]
    const int bb = bh >> 4;          // bh / NHEAD
    const int h  = bh & (NHEAD - 1);
#pragma unroll
    for (int i = 0; i < 4; i++) {
        const float inv = 1.0f / l_[i];
        const int row = bb * SEQ + q0 + ty * 4 + i;
        const int colb = h * HD + tx * 4;
#pragma unroll
        for (int j = 0; j < 4; j++)
            out[(size_t)row * D_MODEL + colb + j] = o_[i][j] * inv;
    }
}

// ---------------------------------------------------------------------------
extern "C" void kernel_launch(void* const* d_in, const int* in_sizes, int n_in,
                              void* d_out, int out_size)
{
    (void)in_sizes; (void)n_in; (void)out_size;
    const float* x  = (const float*)d_in[0];
    const float* Wq = (const float*)d_in[1];
    const float* bq = (const float*)d_in[2];
    const float* Wk = (const float*)d_in[3];
    const float* bk = (const float*)d_in[4];
    const float* Wv = (const float*)d_in[5];
    const float* bv = (const float*)d_in[6];
    const float* Wo = (const float*)d_in[7];
    const float* bo = (const float*)d_in[8];
    float* out = (float*)d_out;

    float *qp, *kp, *vp, *ap;
    cudaGetSymbolAddress((void**)&qp, g_Q);
    cudaGetSymbolAddress((void**)&kp, g_K);
    cudaGetSymbolAddress((void**)&vp, g_V);
    cudaGetSymbolAddress((void**)&ap, g_A);

    cudaFuncSetAttribute(attn_kernel,
                         cudaFuncAttributeMaxDynamicSharedMemorySize,
                         ATTN_SMEM_BYTES);

    const dim3 gridG(D_MODEL / 64, MTOT / 64);   // (16, 64)
    gemm_bias_kernel<1><<<gridG, 256>>>(x, Wq, bq, qp);
    gemm_bias_kernel<1><<<gridG, 256>>>(x, Wk, bk, kp);
    gemm_bias_kernel<1><<<gridG, 256>>>(x, Wv, bv, vp);

    const dim3 gridA(SEQ / 64, BH);              // (32, 32)
    attn_kernel<<<gridA, 256, ATTN_SMEM_BYTES>>>(qp, kp, vp, ap);

    gemm_bias_kernel<0><<<gridG, 256>>>(ap, Wo, bo, out);
}

// round 4
// speedup vs baseline: 1.5462x; 1.5462x over previous
#include <cuda_runtime.h>
#include <cstdint>
#include <math.h>

#define D_MODEL 1024
#define SEQ     2048
#define BATCH   2
#define NHEAD   16
#define HD      64
#define MTOT    (BATCH * SEQ)   // 4096
#define BH      (BATCH * NHEAD) // 32

// ---- GEMM tiling (tf32 mma.sync) ----
#define BM 128
#define BN 128
#define BK 32
#define KI (D_MODEL / BK)        // 32
#define AS_STRIDE 40             // floats per A smem row (BK + 8)
#define BS_STRIDE 136            // floats per B smem row (BN + 8)
#define AS_FLOATS (BM * AS_STRIDE)        // 5120
#define BS_FLOATS (BK * BS_STRIDE)        // 4352
#define STAGE_FLOATS (AS_FLOATS + BS_FLOATS)
#define GEMM_SMEM (2 * STAGE_FLOATS * 4)  // 75776 bytes

// ---- scratch (__device__ globals; allocation-free rule) ----
__device__ __align__(1024) float g_Q[(size_t)BH * SEQ * HD];
__device__ __align__(1024) float g_K[(size_t)BH * SEQ * HD];
__device__ __align__(1024) float g_V[(size_t)BH * SEQ * HD];
__device__ __align__(1024) float g_A[(size_t)MTOT * D_MODEL];
__device__ __align__(1024) float g_Xc[(size_t)MTOT * D_MODEL];    // tf32-rounded activations
__device__ __align__(1024) float g_Wc[(size_t)D_MODEL * D_MODEL]; // tf32-rounded weights

__device__ __forceinline__ uint32_t s2u(const void* p) {
    uint32_t a;
    asm("{ .reg .u64 t; cvta.to.shared.u64 t, %1; cvt.u32.u64 %0, t; }" : "=r"(a) : "l"(p));
    return a;
}

#define CP_ASYNC16(dst, src) \
    asm volatile("cp.async.ca.shared.global [%0], [%1], 16;" :: "r"(dst), "l"(src) : "memory")
#define CP_COMMIT()  asm volatile("cp.async.commit_group;" ::: "memory")
#define CP_WAIT(N)   asm volatile("cp.async.wait_group %0;" :: "n"(N) : "memory")

__device__ __forceinline__ void mma_tf32(float* d, const uint32_t* a, const uint32_t* b) {
    asm volatile(
        "mma.sync.aligned.m16n8k8.row.col.f32.tf32.tf32.f32 "
        "{%0,%1,%2,%3}, {%4,%5,%6,%7}, {%8,%9}, {%0,%1,%2,%3};"
        : "+f"(d[0]), "+f"(d[1]), "+f"(d[2]), "+f"(d[3])
        : "r"(a[0]), "r"(a[1]), "r"(a[2]), "r"(a[3]), "r"(b[0]), "r"(b[1]));
}

// ---------------------------------------------------------------------------
// tf32 rounding pre-pass (round-to-nearest, unbiased)
// ---------------------------------------------------------------------------
__global__ void __launch_bounds__(256) cvt_tf32(const float4* __restrict__ src,
                                                float4* __restrict__ dst, int n4)
{
    const int i = blockIdx.x * 256 + threadIdx.x;
    if (i < n4) {
        float4 v = src[i];
        asm("cvt.rna.tf32.f32 %0, %0;" : "+f"(v.x));
        asm("cvt.rna.tf32.f32 %0, %0;" : "+f"(v.y));
        asm("cvt.rna.tf32.f32 %0, %0;" : "+f"(v.z));
        asm("cvt.rna.tf32.f32 %0, %0;" : "+f"(v.w));
        dst[i] = v;
    }
}

// ---------------------------------------------------------------------------
// tf32 mma.sync GEMM: out = A[4096,1024] * W[1024,1024] + bias
// 128 threads = 4 warps (2x2), warp tile 64x64 (4 m16 x 8 n8 mma tiles).
// MODE 0: row-major out [M,N]. MODE 1: scatter to [bh, t, hd].
// ---------------------------------------------------------------------------
template <int MODE>
__global__ void __launch_bounds__(128) gemm_tc(
    const float* __restrict__ A, const float* __restrict__ W,
    const float* __restrict__ bias, float* __restrict__ out)
{
    extern __shared__ __align__(16) float smem[];
    float* As[2] = { smem, smem + STAGE_FLOATS };
    float* Bs[2] = { smem + AS_FLOATS, smem + STAGE_FLOATS + AS_FLOATS };

    const int tid = threadIdx.x;
    const int wid = tid >> 5, lane = tid & 31;
    const int wm = wid >> 1, wn = wid & 1;         // 2x2 warp grid
    const int grp = lane >> 2, tg = lane & 3;
    const int nblk = blockIdx.x, mblk = blockIdx.y;

    const float* Ag = A + (size_t)mblk * BM * D_MODEL;
    const float* Wg = W + nblk * BN;

    auto load_stage = [&](int s, int k0) {
        float* as = As[s];
        float* bs = Bs[s];
#pragma unroll
        for (int j = 0; j < 8; j++) {
            const int c = tid + j * 128;
            const int r = c >> 3, q = c & 7;           // A: row 0..127, quad 0..7
            CP_ASYNC16(s2u(&as[r * AS_STRIDE + q * 4]),
                       &Ag[(size_t)r * D_MODEL + k0 + q * 4]);
        }
#pragma unroll
        for (int j = 0; j < 8; j++) {
            const int c = tid + j * 128;
            const int r = c >> 5, q = c & 31;          // B: row 0..31, quad 0..31
            CP_ASYNC16(s2u(&bs[r * BS_STRIDE + q * 4]),
                       &Wg[(size_t)(k0 + r) * D_MODEL + q * 4]);
        }
        CP_COMMIT();
    };

    float acc[4][8][4];
#pragma unroll
    for (int i = 0; i < 4; i++)
#pragma unroll
        for (int j = 0; j < 8; j++)
#pragma unroll
            for (int r = 0; r < 4; r++) acc[i][j][r] = 0.0f;

    load_stage(0, 0);

    for (int kt = 0; kt < KI; kt++) {
        if (kt + 1 < KI) {
            load_stage((kt + 1) & 1, (kt + 1) * BK);
            CP_WAIT(1);
        } else {
            CP_WAIT(0);
        }
        __syncthreads();

        const float* as = As[kt & 1];
        const float* bs = Bs[kt & 1];
#pragma unroll
        for (int kk = 0; kk < BK; kk += 8) {
            uint32_t af[4][4], bf[8][2];
#pragma unroll
            for (int mi = 0; mi < 4; mi++) {
                const int r0 = wm * 64 + mi * 16 + grp;
                af[mi][0] = __float_as_uint(as[r0 * AS_STRIDE + kk + tg]);
                af[mi][1] = __float_as_uint(as[(r0 + 8) * AS_STRIDE + kk + tg]);
                af[mi][2] = __float_as_uint(as[r0 * AS_STRIDE + kk + tg + 4]);
                af[mi][3] = __float_as_uint(as[(r0 + 8) * AS_STRIDE + kk + tg + 4]);
            }
#pragma unroll
            for (int nj = 0; nj < 8; nj++) {
                const int n0 = wn * 64 + nj * 8 + grp;
                bf[nj][0] = __float_as_uint(bs[(kk + tg) * BS_STRIDE + n0]);
                bf[nj][1] = __float_as_uint(bs[(kk + tg + 4) * BS_STRIDE + n0]);
            }
#pragma unroll
            for (int mi = 0; mi < 4; mi++)
#pragma unroll
                for (int nj = 0; nj < 8; nj++)
                    mma_tf32(acc[mi][nj], af[mi], bf[nj]);
        }
        __syncthreads();
    }

    // epilogue: c-frag (row=grp(+8), col=2*tg(+1)) + bias, float2 stores
#pragma unroll
    for (int mi = 0; mi < 4; mi++) {
#pragma unroll
        for (int half = 0; half < 2; half++) {
            const int m = mblk * BM + wm * 64 + mi * 16 + grp + half * 8;
#pragma unroll
            for (int nj = 0; nj < 8; nj++) {
                const int n = nblk * BN + wn * 64 + nj * 8 + 2 * tg;
                float2 v;
                v.x = acc[mi][nj][half * 2 + 0] + bias[n];
                v.y = acc[mi][nj][half * 2 + 1] + bias[n + 1];
                if (MODE == 0) {
                    *(float2*)&out[(size_t)m * D_MODEL + n] = v;
                } else {
                    const int bb = m >> 11, t = m & (SEQ - 1);
                    const int h = n >> 6, hd = n & (HD - 1);
                    *(float2*)&out[(((size_t)(bb * NHEAD + h)) * SEQ + t) * HD + hd] = v;
                }
            }
        }
    }
}

// ---------------------------------------------------------------------------
// Flash-style attention (fp32 SIMT, validated round 1). Q/K/V: [bh, SEQ, HD].
// ---------------------------------------------------------------------------
#define ATTN_SMEM_FLOATS (64 * 64 + 64 * 65 + 64 * 64)
#define ATTN_SMEM_BYTES  (ATTN_SMEM_FLOATS * 4)

__global__ void __launch_bounds__(256) attn_kernel(
    const float* __restrict__ Q, const float* __restrict__ K,
    const float* __restrict__ V, float* __restrict__ out)
{
    extern __shared__ float sm[];
    float* Qs = sm;
    float* Ks = sm + 64 * 64;
    float* Ps = Ks;
    float* Vs = Ks + 64 * 65;

    const int tid = threadIdx.x;
    const int tx = tid & 15, ty = tid >> 4;
    const int bh = blockIdx.y;
    const int q0 = blockIdx.x * 64;

    const float* Qp = Q + ((size_t)bh * SEQ + q0) * HD;
    const float* Kp = K + (size_t)bh * SEQ * HD;
    const float* Vp = V + (size_t)bh * SEQ * HD;

    for (int i = tid * 4; i < 64 * HD; i += 256 * 4) {
        const int r = i >> 6, c = i & 63;
        float4 v4 = *(const float4*)&Qp[(size_t)r * HD + c];
        v4.x *= 0.125f; v4.y *= 0.125f; v4.z *= 0.125f; v4.w *= 0.125f;
        *(float4*)&Qs[r * 64 + c] = v4;
    }

    float m_[4], l_[4], o_[4][4];
#pragma unroll
    for (int i = 0; i < 4; i++) {
        m_[i] = -1e30f; l_[i] = 0.0f;
#pragma unroll
        for (int j = 0; j < 4; j++) o_[i][j] = 0.0f;
    }
    __syncthreads();

    for (int kt = 0; kt < SEQ; kt += 64) {
        for (int i = tid * 4; i < 64 * HD; i += 256 * 4) {
            const int r = i >> 6, c = i & 63;
            float4 kv = *(const float4*)&Kp[(size_t)(kt + r) * HD + c];
            Ks[r * 65 + c + 0] = kv.x;
            Ks[r * 65 + c + 1] = kv.y;
            Ks[r * 65 + c + 2] = kv.z;
            Ks[r * 65 + c + 3] = kv.w;
            *(float4*)&Vs[r * 64 + c] = *(const float4*)&Vp[(size_t)(kt + r) * HD + c];
        }
        __syncthreads();

        float s[4][4] = {};
#pragma unroll 8
        for (int d = 0; d < 64; d++) {
            float a[4], b[4];
#pragma unroll
            for (int i = 0; i < 4; i++) a[i] = Qs[(ty * 4 + i) * 64 + d];
#pragma unroll
            for (int j = 0; j < 4; j++) b[j] = Ks[(tx * 4 + j) * 65 + d];
#pragma unroll
            for (int i = 0; i < 4; i++)
#pragma unroll
                for (int j = 0; j < 4; j++)
                    s[i][j] = fmaf(a[i], b[j], s[i][j]);
        }
        __syncthreads();

#pragma unroll
        for (int i = 0; i < 4; i++) {
            float mx = fmaxf(fmaxf(s[i][0], s[i][1]), fmaxf(s[i][2], s[i][3]));
#pragma unroll
            for (int o = 1; o < 16; o <<= 1)
                mx = fmaxf(mx, __shfl_xor_sync(0xffffffffu, mx, o));
            const float mnew = fmaxf(m_[i], mx);
            const float alpha = __expf(m_[i] - mnew);
            float p[4];
            float rs = 0.0f;
#pragma unroll
            for (int j = 0; j < 4; j++) { p[j] = __expf(s[i][j] - mnew); rs += p[j]; }
#pragma unroll
            for (int o = 1; o < 16; o <<= 1)
                rs += __shfl_xor_sync(0xffffffffu, rs, o);
            l_[i] = l_[i] * alpha + rs;
            m_[i] = mnew;
#pragma unroll
            for (int j = 0; j < 4; j++) {
                o_[i][j] *= alpha;
                Ps[(ty * 4 + i) * 64 + tx * 4 + j] = p[j];
            }
        }
        __syncthreads();

#pragma unroll 8
        for (int k = 0; k < 64; k++) {
            float a[4];
#pragma unroll
            for (int i = 0; i < 4; i++) a[i] = Ps[(ty * 4 + i) * 64 + k];
            const float4 b4 = *(const float4*)&Vs[k * 64 + tx * 4];
            const float b[4] = {b4.x, b4.y, b4.z, b4.w};
#pragma unroll
            for (int i = 0; i < 4; i++)
#pragma unroll
                for (int j = 0; j < 4; j++)
                    o_[i][j] = fmaf(a[i], b[j], o_[i][j]);
        }
        __syncthreads();
    }

    const int bb = bh >> 4;
    const int h  = bh & (NHEAD - 1);
#pragma unroll
    for (int i = 0; i < 4; i++) {
        const float inv = 1.0f / l_[i];
        const int row = bb * SEQ + q0 + ty * 4 + i;
        const int colb = h * HD + tx * 4;
#pragma unroll
        for (int j = 0; j < 4; j++)
            out[(size_t)row * D_MODEL + colb + j] = o_[i][j] * inv;
    }
}

// ---------------------------------------------------------------------------
extern "C" void kernel_launch(void* const* d_in, const int* in_sizes, int n_in,
                              void* d_out, int out_size)
{
    (void)in_sizes; (void)n_in; (void)out_size;
    const float* x  = (const float*)d_in[0];
    const float* Wq = (const float*)d_in[1];
    const float* bq = (const float*)d_in[2];
    const float* Wk = (const float*)d_in[3];
    const float* bk = (const float*)d_in[4];
    const float* Wv = (const float*)d_in[5];
    const float* bv = (const float*)d_in[6];
    const float* Wo = (const float*)d_in[7];
    const float* bo = (const float*)d_in[8];
    float* out = (float*)d_out;

    float *qp, *kp, *vp, *ap, *xc, *wc;
    cudaGetSymbolAddress((void**)&qp, g_Q);
    cudaGetSymbolAddress((void**)&kp, g_K);
    cudaGetSymbolAddress((void**)&vp, g_V);
    cudaGetSymbolAddress((void**)&ap, g_A);
    cudaGetSymbolAddress((void**)&xc, g_Xc);
    cudaGetSymbolAddress((void**)&wc, g_Wc);

    cudaFuncSetAttribute(gemm_tc<0>, cudaFuncAttributeMaxDynamicSharedMemorySize, GEMM_SMEM);
    cudaFuncSetAttribute(gemm_tc<1>, cudaFuncAttributeMaxDynamicSharedMemorySize, GEMM_SMEM);
    cudaFuncSetAttribute(attn_kernel, cudaFuncAttributeMaxDynamicSharedMemorySize, ATTN_SMEM_BYTES);

    const int NX4 = MTOT * D_MODEL / 4;     // 1,048,576
    const int NW4 = D_MODEL * D_MODEL / 4;  // 262,144
    const dim3 gridG(D_MODEL / BN, MTOT / BM);   // (8, 32)

    cvt_tf32<<<NX4 / 256, 256>>>((const float4*)x, (float4*)xc, NX4);

    cvt_tf32<<<NW4 / 256, 256>>>((const float4*)Wq, (float4*)wc, NW4);
    gemm_tc<1><<<gridG, 128, GEMM_SMEM>>>(xc, wc, bq, qp);
    cvt_tf32<<<NW4 / 256, 256>>>((const float4*)Wk, (float4*)wc, NW4);
    gemm_tc<1><<<gridG, 128, GEMM_SMEM>>>(xc, wc, bk, kp);
    cvt_tf32<<<NW4 / 256, 256>>>((const float4*)Wv, (float4*)wc, NW4);
    gemm_tc<1><<<gridG, 128, GEMM_SMEM>>>(xc, wc, bv, vp);

    const dim3 gridA(SEQ / 64, BH);              // (32, 32)
    attn_kernel<<<gridA, 256, ATTN_SMEM_BYTES>>>(qp, kp, vp, ap);

    cvt_tf32<<<NX4 / 256, 256>>>((const float4*)ap, (float4*)xc, NX4);
    cvt_tf32<<<NW4 / 256, 256>>>((const float4*)Wo, (float4*)wc, NW4);
    gemm_tc<0><<<gridG, 128, GEMM_SMEM>>>(xc, wc, bo, out);
}

// round 5
// speedup vs baseline: 3.2003x; 2.0698x over previous
#include <cuda_runtime.h>
#include <cstdint>
#include <math.h>

#define D_MODEL 1024
#define SEQ     2048
#define BATCH   2
#define NHEAD   16
#define HD      64
#define MTOT    (BATCH * SEQ)   // 4096
#define BH      (BATCH * NHEAD) // 32

// ---- GEMM tiling (tf32 mma.sync) ----
#define BM 128
#define BN 128
#define BK 32
#define KI (D_MODEL / BK)        // 32
#define AS_STRIDE 40
#define BS_STRIDE 136
#define AS_FLOATS (BM * AS_STRIDE)
#define BS_FLOATS (BK * BS_STRIDE)
#define STAGE_FLOATS (AS_FLOATS + BS_FLOATS)
#define GEMM_SMEM (2 * STAGE_FLOATS * 4)

// ---- attention tiling ----
#define AQ 128                   // q-rows per CTA
#define AK 64                    // keys per k-tile
#define QS_STRIDE 68
#define PS_STRIDE 68             // P / K union region
#define VS_STRIDE 72
#define ATTN_SMEM ((AQ * QS_STRIDE + AQ * PS_STRIDE + AK * VS_STRIDE) * 4) // 88064

// ---- scratch ----
__device__ __align__(1024) float g_Q[(size_t)BH * SEQ * HD];
__device__ __align__(1024) float g_K[(size_t)BH * SEQ * HD];
__device__ __align__(1024) float g_V[(size_t)BH * SEQ * HD];
__device__ __align__(1024) float g_A[(size_t)MTOT * D_MODEL];
__device__ __align__(1024) float g_Xc[(size_t)MTOT * D_MODEL];
__device__ __align__(1024) float g_Wc[(size_t)D_MODEL * D_MODEL];

__device__ __forceinline__ uint32_t s2u(const void* p) {
    uint32_t a;
    asm("{ .reg .u64 t; cvta.to.shared.u64 t, %1; cvt.u32.u64 %0, t; }" : "=r"(a) : "l"(p));
    return a;
}
__device__ __forceinline__ float rna(float x) {
    asm("cvt.rna.tf32.f32 %0, %0;" : "+f"(x));
    return x;
}

#define CP_ASYNC16(dst, src) \
    asm volatile("cp.async.ca.shared.global [%0], [%1], 16;" :: "r"(dst), "l"(src) : "memory")
#define CP_COMMIT()  asm volatile("cp.async.commit_group;" ::: "memory")
#define CP_WAIT(N)   asm volatile("cp.async.wait_group %0;" :: "n"(N) : "memory")

__device__ __forceinline__ void mma_tf32(float* d, const uint32_t* a, const uint32_t* b) {
    asm volatile(
        "mma.sync.aligned.m16n8k8.row.col.f32.tf32.tf32.f32 "
        "{%0,%1,%2,%3}, {%4,%5,%6,%7}, {%8,%9}, {%0,%1,%2,%3};"
        : "+f"(d[0]), "+f"(d[1]), "+f"(d[2]), "+f"(d[3])
        : "r"(a[0]), "r"(a[1]), "r"(a[2]), "r"(a[3]), "r"(b[0]), "r"(b[1]));
}

// ---------------------------------------------------------------------------
__global__ void __launch_bounds__(256) cvt_tf32(const float4* __restrict__ src,
                                                float4* __restrict__ dst, int n4)
{
    const int i = blockIdx.x * 256 + threadIdx.x;
    if (i < n4) {
        float4 v = src[i];
        v.x = rna(v.x); v.y = rna(v.y); v.z = rna(v.z); v.w = rna(v.w);
        dst[i] = v;
    }
}

// ---------------------------------------------------------------------------
// tf32 mma.sync GEMM (validated round 4).
// ---------------------------------------------------------------------------
template <int MODE>
__global__ void __launch_bounds__(128) gemm_tc(
    const float* __restrict__ A, const float* __restrict__ W,
    const float* __restrict__ bias, float* __restrict__ out)
{
    extern __shared__ __align__(16) float smem[];
    float* As[2] = { smem, smem + STAGE_FLOATS };
    float* Bs[2] = { smem + AS_FLOATS, smem + STAGE_FLOATS + AS_FLOATS };

    const int tid = threadIdx.x;
    const int wid = tid >> 5, lane = tid & 31;
    const int wm = wid >> 1, wn = wid & 1;
    const int grp = lane >> 2, tg = lane & 3;
    const int nblk = blockIdx.x, mblk = blockIdx.y;

    const float* Ag = A + (size_t)mblk * BM * D_MODEL;
    const float* Wg = W + nblk * BN;

    auto load_stage = [&](int s, int k0) {
        float* as = As[s];
        float* bs = Bs[s];
#pragma unroll
        for (int j = 0; j < 8; j++) {
            const int c = tid + j * 128;
            const int r = c >> 3, q = c & 7;
            CP_ASYNC16(s2u(&as[r * AS_STRIDE + q * 4]),
                       &Ag[(size_t)r * D_MODEL + k0 + q * 4]);
        }
#pragma unroll
        for (int j = 0; j < 8; j++) {
            const int c = tid + j * 128;
            const int r = c >> 5, q = c & 31;
            CP_ASYNC16(s2u(&bs[r * BS_STRIDE + q * 4]),
                       &Wg[(size_t)(k0 + r) * D_MODEL + q * 4]);
        }
        CP_COMMIT();
    };

    float acc[4][8][4];
#pragma unroll
    for (int i = 0; i < 4; i++)
#pragma unroll
        for (int j = 0; j < 8; j++)
#pragma unroll
            for (int r = 0; r < 4; r++) acc[i][j][r] = 0.0f;

    load_stage(0, 0);

    for (int kt = 0; kt < KI; kt++) {
        if (kt + 1 < KI) {
            load_stage((kt + 1) & 1, (kt + 1) * BK);
            CP_WAIT(1);
        } else {
            CP_WAIT(0);
        }
        __syncthreads();

        const float* as = As[kt & 1];
        const float* bs = Bs[kt & 1];
#pragma unroll
        for (int kk = 0; kk < BK; kk += 8) {
            uint32_t af[4][4], bf[8][2];
#pragma unroll
            for (int mi = 0; mi < 4; mi++) {
                const int r0 = wm * 64 + mi * 16 + grp;
                af[mi][0] = __float_as_uint(as[r0 * AS_STRIDE + kk + tg]);
                af[mi][1] = __float_as_uint(as[(r0 + 8) * AS_STRIDE + kk + tg]);
                af[mi][2] = __float_as_uint(as[r0 * AS_STRIDE + kk + tg + 4]);
                af[mi][3] = __float_as_uint(as[(r0 + 8) * AS_STRIDE + kk + tg + 4]);
            }
#pragma unroll
            for (int nj = 0; nj < 8; nj++) {
                const int n0 = wn * 64 + nj * 8 + grp;
                bf[nj][0] = __float_as_uint(bs[(kk + tg) * BS_STRIDE + n0]);
                bf[nj][1] = __float_as_uint(bs[(kk + tg + 4) * BS_STRIDE + n0]);
            }
#pragma unroll
            for (int mi = 0; mi < 4; mi++)
#pragma unroll
                for (int nj = 0; nj < 8; nj++)
                    mma_tf32(acc[mi][nj], af[mi], bf[nj]);
        }
        __syncthreads();
    }

#pragma unroll
    for (int mi = 0; mi < 4; mi++) {
#pragma unroll
        for (int half = 0; half < 2; half++) {
            const int m = mblk * BM + wm * 64 + mi * 16 + grp + half * 8;
#pragma unroll
            for (int nj = 0; nj < 8; nj++) {
                const int n = nblk * BN + wn * 64 + nj * 8 + 2 * tg;
                float2 v;
                v.x = acc[mi][nj][half * 2 + 0] + bias[n];
                v.y = acc[mi][nj][half * 2 + 1] + bias[n + 1];
                if (MODE == 0) {
                    *(float2*)&out[(size_t)m * D_MODEL + n] = v;
                } else {
                    const int bb = m >> 11, t = m & (SEQ - 1);
                    const int h = n >> 6, hd = n & (HD - 1);
                    *(float2*)&out[(((size_t)(bb * NHEAD + h)) * SEQ + t) * HD + hd] = v;
                }
            }
        }
    }
}

// ---------------------------------------------------------------------------
// tf32 mma.sync flash attention.
// Q/K/V: [bh, SEQ, HD] fp32. Out: g_A [4096, 1024], pre-rounded to tf32.
// CTA: 128 q-rows x 1 bh; 8 warps; warp tile 16 q-rows x 64 keys.
// Smem: Qs[128][68] | Ps[128][68] (rows 0..63 double as Ks) | Vs[64][72].
// ---------------------------------------------------------------------------
__global__ void __launch_bounds__(256, 2) attn_kernel(
    const float* __restrict__ Q, const float* __restrict__ K,
    const float* __restrict__ V, float* __restrict__ out)
{
    extern __shared__ __align__(16) float sm[];
    float* Qs = sm;                         // [128][68]
    float* Ps = sm + AQ * QS_STRIDE;        // [128][68]; Ks = rows 0..63
    float* Vs = Ps + AQ * PS_STRIDE;        // [64][72]

    const int tid = threadIdx.x;
    const int w = tid >> 5, lane = tid & 31;
    const int grp = lane >> 2, tg = lane & 3;
    const int bh = blockIdx.y;
    const int q0 = blockIdx.x * AQ;

    const float* Qp = Q + ((size_t)bh * SEQ + q0) * HD;
    const float* Kp = K + (size_t)bh * SEQ * HD;
    const float* Vp = V + (size_t)bh * SEQ * HD;

    // Load Q tile (fold softmax scale 0.125, round to tf32)
#pragma unroll
    for (int it = 0; it < 8; it++) {
        const int idx = tid + it * 256;       // 2048 float4
        const int r = idx >> 4, c4 = (idx & 15) * 4;
        float4 v = *(const float4*)&Qp[(size_t)r * HD + c4];
        v.x = rna(v.x * 0.125f); v.y = rna(v.y * 0.125f);
        v.z = rna(v.z * 0.125f); v.w = rna(v.w * 0.125f);
        *(float4*)&Qs[r * QS_STRIDE + c4] = v;
    }

    float o[8][4];
#pragma unroll
    for (int nj = 0; nj < 8; nj++)
#pragma unroll
        for (int r = 0; r < 4; r++) o[nj][r] = 0.0f;
    float m_lo = -1e30f, m_hi = -1e30f, l_lo = 0.0f, l_hi = 0.0f;

    const int row0 = w * 16 + grp;           // warp's A-frag rows: row0, row0+8

    for (int kt = 0; kt < SEQ; kt += AK) {
        // Load K tile -> Ps rows 0..63, V tile -> Vs (both rounded)
#pragma unroll
        for (int it = 0; it < 4; it++) {
            const int idx = tid + it * 256;   // 1024 float4
            const int r = idx >> 4, c4 = (idx & 15) * 4;
            float4 kv = *(const float4*)&Kp[(size_t)(kt + r) * HD + c4];
            kv.x = rna(kv.x); kv.y = rna(kv.y); kv.z = rna(kv.z); kv.w = rna(kv.w);
            *(float4*)&Ps[r * PS_STRIDE + c4] = kv;
            float4 vv = *(const float4*)&Vp[(size_t)(kt + r) * HD + c4];
            vv.x = rna(vv.x); vv.y = rna(vv.y); vv.z = rna(vv.z); vv.w = rna(vv.w);
            *(float4*)&Vs[r * VS_STRIDE + c4] = vv;
        }
        __syncthreads();

        // S = Q * K^T  (warp: 16 rows x 64 keys)
        float s[8][4];
#pragma unroll
        for (int nj = 0; nj < 8; nj++)
#pragma unroll
            for (int r = 0; r < 4; r++) s[nj][r] = 0.0f;

#pragma unroll
        for (int kk = 0; kk < HD; kk += 8) {
            uint32_t af[4], bf[8][2];
            af[0] = __float_as_uint(Qs[row0 * QS_STRIDE + kk + tg]);
            af[1] = __float_as_uint(Qs[(row0 + 8) * QS_STRIDE + kk + tg]);
            af[2] = __float_as_uint(Qs[row0 * QS_STRIDE + kk + tg + 4]);
            af[3] = __float_as_uint(Qs[(row0 + 8) * QS_STRIDE + kk + tg + 4]);
#pragma unroll
            for (int nj = 0; nj < 8; nj++) {
                const int n0 = nj * 8 + grp;
                bf[nj][0] = __float_as_uint(Ps[n0 * PS_STRIDE + kk + tg]);
                bf[nj][1] = __float_as_uint(Ps[n0 * PS_STRIDE + kk + tg + 4]);
            }
#pragma unroll
            for (int nj = 0; nj < 8; nj++)
                mma_tf32(s[nj], af, bf[nj]);
        }
        __syncthreads();   // all Ks reads complete before P overwrites rows 0..63

        // Online softmax (rows grp -> regs 0,1 ; grp+8 -> regs 2,3)
        float mx_lo = -1e30f, mx_hi = -1e30f;
#pragma unroll
        for (int nj = 0; nj < 8; nj++) {
            mx_lo = fmaxf(mx_lo, fmaxf(s[nj][0], s[nj][1]));
            mx_hi = fmaxf(mx_hi, fmaxf(s[nj][2], s[nj][3]));
        }
#pragma unroll
        for (int off = 1; off < 4; off <<= 1) {
            mx_lo = fmaxf(mx_lo, __shfl_xor_sync(0xffffffffu, mx_lo, off));
            mx_hi = fmaxf(mx_hi, __shfl_xor_sync(0xffffffffu, mx_hi, off));
        }
        const float mn_lo = fmaxf(m_lo, mx_lo);
        const float mn_hi = fmaxf(m_hi, mx_hi);
        const float al_lo = __expf(m_lo - mn_lo);
        const float al_hi = __expf(m_hi - mn_hi);

        float rs_lo = 0.0f, rs_hi = 0.0f;
#pragma unroll
        for (int nj = 0; nj < 8; nj++) {
            s[nj][0] = __expf(s[nj][0] - mn_lo);
            s[nj][1] = __expf(s[nj][1] - mn_lo);
            s[nj][2] = __expf(s[nj][2] - mn_hi);
            s[nj][3] = __expf(s[nj][3] - mn_hi);
            rs_lo += s[nj][0] + s[nj][1];
            rs_hi += s[nj][2] + s[nj][3];
        }
#pragma unroll
        for (int off = 1; off < 4; off <<= 1) {
            rs_lo += __shfl_xor_sync(0xffffffffu, rs_lo, off);
            rs_hi += __shfl_xor_sync(0xffffffffu, rs_hi, off);
        }
        l_lo = l_lo * al_lo + rs_lo;
        l_hi = l_hi * al_hi + rs_hi;
        m_lo = mn_lo;
        m_hi = mn_hi;

        // Rescale O, store rounded P to smem (own 16 rows only)
#pragma unroll
        for (int nj = 0; nj < 8; nj++) {
            o[nj][0] *= al_lo; o[nj][1] *= al_lo;
            o[nj][2] *= al_hi; o[nj][3] *= al_hi;
            float2 plo = { rna(s[nj][0]), rna(s[nj][1]) };
            float2 phi = { rna(s[nj][2]), rna(s[nj][3]) };
            *(float2*)&Ps[row0 * PS_STRIDE + nj * 8 + 2 * tg] = plo;
            *(float2*)&Ps[(row0 + 8) * PS_STRIDE + nj * 8 + 2 * tg] = phi;
        }
        __syncwarp();

        // O += P * V
#pragma unroll
        for (int kk = 0; kk < AK; kk += 8) {
            uint32_t af[4], bf[8][2];
            af[0] = __float_as_uint(Ps[row0 * PS_STRIDE + kk + tg]);
            af[1] = __float_as_uint(Ps[(row0 + 8) * PS_STRIDE + kk + tg]);
            af[2] = __float_as_uint(Ps[row0 * PS_STRIDE + kk + tg + 4]);
            af[3] = __float_as_uint(Ps[(row0 + 8) * PS_STRIDE + kk + tg + 4]);
#pragma unroll
            for (int nj = 0; nj < 8; nj++) {
                const int n0 = nj * 8 + grp;
                bf[nj][0] = __float_as_uint(Vs[(kk + tg) * VS_STRIDE + n0]);
                bf[nj][1] = __float_as_uint(Vs[(kk + tg + 4) * VS_STRIDE + n0]);
            }
#pragma unroll
            for (int nj = 0; nj < 8; nj++)
                mma_tf32(o[nj], af, bf[nj]);
        }
        __syncthreads();   // P reads done before next K load overwrites
    }

    // Normalize, round to tf32, scatter to [4096, 1024]
    const int bb = bh >> 4;
    const int h  = bh & (NHEAD - 1);
    const float inv_lo = 1.0f / l_lo;
    const float inv_hi = 1.0f / l_hi;
    const int grow_lo = bb * SEQ + q0 + row0;
    const int colb = h * HD;
#pragma unroll
    for (int nj = 0; nj < 8; nj++) {
        const int col = colb + nj * 8 + 2 * tg;
        float2 vlo = { rna(o[nj][0] * inv_lo), rna(o[nj][1] * inv_lo) };
        float2 vhi = { rna(o[nj][2] * inv_hi), rna(o[nj][3] * inv_hi) };
        *(float2*)&out[(size_t)grow_lo * D_MODEL + col] = vlo;
        *(float2*)&out[(size_t)(grow_lo + 8) * D_MODEL + col] = vhi;
    }
}

// ---------------------------------------------------------------------------
extern "C" void kernel_launch(void* const* d_in, const int* in_sizes, int n_in,
                              void* d_out, int out_size)
{
    (void)in_sizes; (void)n_in; (void)out_size;
    const float* x  = (const float*)d_in[0];
    const float* Wq = (const float*)d_in[1];
    const float* bq = (const float*)d_in[2];
    const float* Wk = (const float*)d_in[3];
    const float* bk = (const float*)d_in[4];
    const float* Wv = (const float*)d_in[5];
    const float* bv = (const float*)d_in[6];
    const float* Wo = (const float*)d_in[7];
    const float* bo = (const float*)d_in[8];
    float* out = (float*)d_out;

    float *qp, *kp, *vp, *ap, *xc, *wc;
    cudaGetSymbolAddress((void**)&qp, g_Q);
    cudaGetSymbolAddress((void**)&kp, g_K);
    cudaGetSymbolAddress((void**)&vp, g_V);
    cudaGetSymbolAddress((void**)&ap, g_A);
    cudaGetSymbolAddress((void**)&xc, g_Xc);
    cudaGetSymbolAddress((void**)&wc, g_Wc);

    cudaFuncSetAttribute(gemm_tc<0>, cudaFuncAttributeMaxDynamicSharedMemorySize, GEMM_SMEM);
    cudaFuncSetAttribute(gemm_tc<1>, cudaFuncAttributeMaxDynamicSharedMemorySize, GEMM_SMEM);
    cudaFuncSetAttribute(attn_kernel, cudaFuncAttributeMaxDynamicSharedMemorySize, ATTN_SMEM);

    const int NX4 = MTOT * D_MODEL / 4;
    const int NW4 = D_MODEL * D_MODEL / 4;
    const dim3 gridG(D_MODEL / BN, MTOT / BM);   // (8, 32)

    cvt_tf32<<<NX4 / 256, 256>>>((const float4*)x, (float4*)xc, NX4);

    cvt_tf32<<<NW4 / 256, 256>>>((const float4*)Wq, (float4*)wc, NW4);
    gemm_tc<1><<<gridG, 128, GEMM_SMEM>>>(xc, wc, bq, qp);
    cvt_tf32<<<NW4 / 256, 256>>>((const float4*)Wk, (float4*)wc, NW4);
    gemm_tc<1><<<gridG, 128, GEMM_SMEM>>>(xc, wc, bk, kp);
    cvt_tf32<<<NW4 / 256, 256>>>((const float4*)Wv, (float4*)wc, NW4);
    gemm_tc<1><<<gridG, 128, GEMM_SMEM>>>(xc, wc, bv, vp);

    const dim3 gridA(SEQ / AQ, BH);              // (16, 32)
    attn_kernel<<<gridA, 256, ATTN_SMEM>>>(qp, kp, vp, ap);

    cvt_tf32<<<NW4 / 256, 256>>>((const float4*)Wo, (float4*)wc, NW4);
    gemm_tc<0><<<gridG, 128, GEMM_SMEM>>>(ap, wc, bo, out);
}